// round 5
// baseline (speedup 1.0000x reference)
#include <cuda_runtime.h>
#include <math.h>
#include <stdint.h>

#define L_TOT  65536
#define HDIM   256
#define WDIM   256
#define DIM    192
#define C1     48
#define NTOK   8

typedef unsigned long long u64t;

__device__ __forceinline__ u64t ffma2(u64t a, u64t b, u64t c) {
    u64t d;
    asm("fma.rn.f32x2 %0, %1, %2, %3;" : "=l"(d) : "l"(a), "l"(b), "l"(c));
    return d;
}
union F2u { u64t u; float2 f; };
__device__ __forceinline__ float lohi_sum(u64t v) { F2u t; t.u = v; return t.f.x + t.f.y; }

// ---------------- scratch ----------------
__device__ float  g_intensity[L_TOT];
__device__ float2 g_f1p[(C1 / 2) * L_TOT];     // conv1 out, ic-pair interleaved [icp][l]
__device__ float  g_feat[(size_t)L_TOT * DIM]; // conv2 out, token-major [l][c]
__device__ float  g_gamma[L_TOT];
__device__ float  g_beta[L_TOT];

// ---------------- K1: intensity ----------------
__global__ void k_intensity(const float* __restrict__ x) {
    int l = blockIdx.x * 256 + threadIdx.x;
    const float* p = x + (size_t)l * DIM;
    g_intensity[l] = 0.299f * p[0] + 0.587f * p[1] + 0.114f * p[2];
}

// ---------------- K2: conv1 1->48, 3x3 SAME, LeakyReLU(0.2) ----------------
__global__ void k_conv1(const float* __restrict__ w, const float* __restrict__ b) {
    int l  = blockIdx.x * 256 + threadIdx.x;
    int oc = blockIdx.y;
    int y = l >> 8, xx = l & 255;
    float acc = b[oc];
    #pragma unroll
    for (int ky = 0; ky < 3; ky++) {
        int gy = y + ky - 1;
        if (gy < 0 || gy >= HDIM) continue;
        #pragma unroll
        for (int kx = 0; kx < 3; kx++) {
            int gx = xx + kx - 1;
            if (gx < 0 || gx >= WDIM) continue;
            acc += w[oc * 9 + ky * 3 + kx] * g_intensity[(gy << 8) + gx];
        }
    }
    acc = (acc > 0.f) ? acc : 0.2f * acc;
    ((float*)g_f1p)[((size_t)(oc >> 1) * L_TOT + l) * 2 + (oc & 1)] = acc;
}

// ---------------- K3: conv2 48->192, 3x3 SAME (ic-pair f32x2 GEMM) ----------------
// Block tile: 128 pixels x 64 oc. Thread tile: 4 pix x 8 oc x 2 ic (packed).
// Ping-pong staging per ic-pair: Ps2[9][128] float2, Ws2[9][64] float2.
__global__ __launch_bounds__(256) void k_conv2(const float* __restrict__ w2,
                                               const float* __restrict__ b2) {
    __shared__ float2 Ps2[2][9][128];
    __shared__ float2 Ws2[2][9][64];
    int tid = threadIdx.x;
    int oc0 = (blockIdx.x % 3) * 64;
    int p0  = (blockIdx.x / 3) * 128;
    int y  = p0 >> 8;
    int x0 = p0 & 255;
    int tx = tid & 7;    // oc: oc0 + tx*8 + j
    int ty = tid >> 3;   // pix: ty*4 + i   (ty 0..31)

    u64t acc[4][8];
    #pragma unroll
    for (int i = 0; i < 4; i++)
        #pragma unroll
        for (int j = 0; j < 8; j++) acc[i][j] = 0ull;

    auto stage = [&](int icp, int buf) {
        for (int idx = tid; idx < 576; idx += 256) {
            int kp = idx >> 6, ocl = idx & 63;
            const float* wr = w2 + (size_t)(oc0 + ocl) * 432 + icp * 18 + kp;
            Ws2[buf][kp][ocl] = make_float2(wr[0], wr[9]);
        }
        for (int idx = tid; idx < 1152; idx += 256) {
            int kp = idx >> 7, p = idx & 127;
            int ky = kp / 3, kx = kp - ky * 3;
            int gy = y + ky - 1, gx = x0 + p + kx - 1;
            float2 v = make_float2(0.f, 0.f);
            if (gy >= 0 && gy < HDIM && gx >= 0 && gx < WDIM)
                v = g_f1p[(size_t)icp * L_TOT + (gy << 8) + gx];
            Ps2[buf][kp][p] = v;
        }
    };

    stage(0, 0);
    __syncthreads();
    for (int icp = 0; icp < 24; icp++) {
        int buf = icp & 1;
        if (icp + 1 < 24) stage(icp + 1, buf ^ 1);
        #pragma unroll
        for (int kp = 0; kp < 9; kp++) {
            u64t a[4];
            #pragma unroll
            for (int i = 0; i < 4; i++)
                a[i] = *(const u64t*)&Ps2[buf][kp][ty * 4 + i];
            const ulonglong2* bp = (const ulonglong2*)&Ws2[buf][kp][tx * 8];
            ulonglong2 b0 = bp[0], b1 = bp[1], b2v = bp[2], b3 = bp[3];
            u64t bv[8] = {b0.x, b0.y, b1.x, b1.y, b2v.x, b2v.y, b3.x, b3.y};
            #pragma unroll
            for (int i = 0; i < 4; i++)
                #pragma unroll
                for (int j = 0; j < 8; j++)
                    acc[i][j] = ffma2(a[i], bv[j], acc[i][j]);
        }
        __syncthreads();
    }

    float bj[8];
    #pragma unroll
    for (int j = 0; j < 8; j++) bj[j] = b2[oc0 + tx * 8 + j];
    #pragma unroll
    for (int i = 0; i < 4; i++) {
        int l = p0 + ty * 4 + i;
        float r[8];
        #pragma unroll
        for (int j = 0; j < 8; j++) r[j] = lohi_sum(acc[i][j]) + bj[j];
        float* op = g_feat + (size_t)l * DIM + oc0 + tx * 8;
        *(float4*)(op + 0) = make_float4(r[0], r[1], r[2], r[3]);
        *(float4*)(op + 4) = make_float4(r[4], r[5], r[6], r[7]);
    }
}

// ---------------- K4: routing MLP + softmax + gumbel argmax ----------------
// 64 tokens/block, 256 threads. GEMM 64x96 k=192 with k-pair f32x2.
__global__ __launch_bounds__(256) void k_route(const float* __restrict__ x,
                                               const float* __restrict__ w1,
                                               const float* __restrict__ b1,
                                               const float* __restrict__ w2,
                                               const float* __restrict__ b2r,
                                               const float* __restrict__ gumbel,
                                               const float* __restrict__ emb) {
    extern __shared__ float sh[];
    float*  z_s  = sh;                          // [64][196]
    float2* W1c  = (float2*)(sh + 64 * 196);    // [32][96]
    float*  hm_s = sh + 64 * 196 + 32 * 96 * 2; // [64][100]
    float*  W2s  = hm_s + 64 * 100;             // [8][96]
    float*  lg_s = W2s + 768;                   // [64][9]

    int tid = threadIdx.x;
    int l0 = blockIdx.x * 64;
    int tx = tid & 15;   // hmid: tx*6 + j
    int ty = tid >> 4;   // tok:  ty*4 + i

    // stage z = x + 0.3*feat
    const float4* x4 = (const float4*)(x + (size_t)l0 * DIM);
    const float4* f4 = (const float4*)(g_feat + (size_t)l0 * DIM);
    for (int idx = tid; idx < 3072; idx += 256) {
        int tok = idx / 48, c4 = idx % 48;
        float4 xv = x4[tok * 48 + c4];
        float4 fv = f4[tok * 48 + c4];
        float4 z;
        z.x = xv.x + 0.3f * fv.x; z.y = xv.y + 0.3f * fv.y;
        z.z = xv.z + 0.3f * fv.z; z.w = xv.w + 0.3f * fv.w;
        *(float4*)&z_s[tok * 196 + c4 * 4] = z;
    }
    for (int idx = tid; idx < 768; idx += 256) W2s[idx] = w2[idx];

    u64t acc[4][6];
    #pragma unroll
    for (int i = 0; i < 4; i++)
        #pragma unroll
        for (int j = 0; j < 6; j++) acc[i][j] = 0ull;

    for (int kc = 0; kc < 3; kc++) {
        __syncthreads();
        for (int idx = tid; idx < 3072; idx += 256) {
            int kp = idx / 96, o = idx % 96;
            W1c[kp * 96 + o] = *(const float2*)&w1[o * DIM + kc * 64 + kp * 2];
        }
        __syncthreads();
        for (int kp = 0; kp < 32; kp += 2) {
            ulonglong2 aA[4];
            #pragma unroll
            for (int i = 0; i < 4; i++)
                aA[i] = *(const ulonglong2*)&z_s[(ty * 4 + i) * 196 + kc * 64 + kp * 2];
            {
                const ulonglong2* bp = (const ulonglong2*)&W1c[kp * 96 + tx * 6];
                ulonglong2 b0 = bp[0], b1v = bp[1], b2v = bp[2];
                u64t bv[6] = {b0.x, b0.y, b1v.x, b1v.y, b2v.x, b2v.y};
                #pragma unroll
                for (int i = 0; i < 4; i++)
                    #pragma unroll
                    for (int j = 0; j < 6; j++)
                        acc[i][j] = ffma2(aA[i].x, bv[j], acc[i][j]);
            }
            {
                const ulonglong2* bp = (const ulonglong2*)&W1c[(kp + 1) * 96 + tx * 6];
                ulonglong2 b0 = bp[0], b1v = bp[1], b2v = bp[2];
                u64t bv[6] = {b0.x, b0.y, b1v.x, b1v.y, b2v.x, b2v.y};
                #pragma unroll
                for (int i = 0; i < 4; i++)
                    #pragma unroll
                    for (int j = 0; j < 6; j++)
                        acc[i][j] = ffma2(aA[i].y, bv[j], acc[i][j]);
            }
        }
    }
    // GELU epilogue -> hm_s
    #pragma unroll
    for (int j = 0; j < 6; j++) {
        float bb = b1[tx * 6 + j];
        #pragma unroll
        for (int i = 0; i < 4; i++) {
            float v = lohi_sum(acc[i][j]) + bb;
            v = 0.5f * v * (1.0f + erff(v * 0.7071067811865476f));
            hm_s[(ty * 4 + i) * 100 + tx * 6 + j] = v;
        }
    }
    __syncthreads();
    // route2: (tok, t) pairs
    #pragma unroll
    for (int half = 0; half < 2; half++) {
        int tok = (tid >> 3) + half * 32;
        int t = tid & 7;
        float s = b2r[t];
        const float4* hp = (const float4*)&hm_s[tok * 100];
        const float4* wp = (const float4*)&W2s[t * 96];
        #pragma unroll 6
        for (int j4 = 0; j4 < 24; j4++) {
            float4 h = hp[j4], w = wp[j4];
            s += h.x * w.x + h.y * w.y + h.z * w.z + h.w * w.w;
        }
        lg_s[tok * 9 + t] = s;
    }
    __syncthreads();
    if (tid < 64) {
        int tok = tid;
        int l = l0 + tok;
        float mx = -1e30f;
        #pragma unroll
        for (int t = 0; t < NTOK; t++) mx = fmaxf(mx, lg_s[tok * 9 + t]);
        float e[NTOK], sum = 0.f;
        #pragma unroll
        for (int t = 0; t < NTOK; t++) { e[t] = expf(lg_s[tok * 9 + t] - mx); sum += e[t]; }
        float inv = 1.0f / sum;
        float inten = g_intensity[l];
        float best = -1e30f; int kbest = 0; float rw0 = 0.f;
        #pragma unroll
        for (int t = 0; t < NTOK; t++) {
            float rw = e[t] * inv;
            if (t == 0) rw0 = rw;
            float sim = 1.0f - fabsf(emb[t] - inten);
            float u = gumbel[(size_t)l * NTOK + t];
            u = fmaxf(u, 1e-10f);
            float g = -logf(-logf(u));
            float sc = rw * sim + g;
            if (sc > best) { best = sc; kbest = t; }
        }
        float ek = emb[kbest];
        g_gamma[l] = 0.3f + 0.7f / (1.0f + expf(-ek));
        g_beta[l]  = rw0 - 0.5f;
    }
}

// ---------------- K5: v=D*(gamma*x+beta), LayerNorm, out = yn@out_w^T + b ----------
// 32 tokens/block, 256 threads. GEMM 32x192 k=192 with k-pair f32x2, tile 2x12.
__global__ __launch_bounds__(256) void k_final(const float* __restrict__ x,
                                               const float* __restrict__ Dv,
                                               const float* __restrict__ ln_w,
                                               const float* __restrict__ ln_b,
                                               const float* __restrict__ out_w,
                                               const float* __restrict__ out_b,
                                               float* __restrict__ out) {
    extern __shared__ float sh[];
    float*  v_s  = sh;                         // [32][196]
    float2* Bs   = (float2*)(sh + 32 * 196);   // [16][192]
    float*  mu_s = sh + 32 * 196 + 16 * 192 * 2; // [32]
    float*  rs_s = mu_s + 32;                  // [32]

    int tid = threadIdx.x;
    int l0 = blockIdx.x * 32;
    int tx = tid & 15;   // oc: tx*12 + j
    int ty = tid >> 4;   // tok: ty*2 + i

    for (int idx = tid; idx < 1536; idx += 256) {
        int tok = idx / 48, c4 = idx % 48;
        int l = l0 + tok;
        float4 xv = *(const float4*)&x[(size_t)l * DIM + c4 * 4];
        float4 dv = *(const float4*)&Dv[c4 * 4];
        float g = g_gamma[l], b = g_beta[l];
        float4 v;
        v.x = dv.x * (g * xv.x + b); v.y = dv.y * (g * xv.y + b);
        v.z = dv.z * (g * xv.z + b); v.w = dv.w * (g * xv.w + b);
        *(float4*)&v_s[tok * 196 + c4 * 4] = v;
    }
    __syncthreads();
    {
        int tok = tid >> 3, l8 = tid & 7;
        float s = 0.f, sq = 0.f;
        for (int c = l8; c < DIM; c += 8) {
            float v = v_s[tok * 196 + c];
            s += v; sq += v * v;
        }
        #pragma unroll
        for (int off = 4; off > 0; off >>= 1) {
            s  += __shfl_down_sync(0xffffffffu, s, off);
            sq += __shfl_down_sync(0xffffffffu, sq, off);
        }
        if (l8 == 0) {
            float mu = s * (1.0f / DIM);
            float var = sq * (1.0f / DIM) - mu * mu;
            mu_s[tok] = mu;
            rs_s[tok] = rsqrtf(var + 1e-5f);
        }
    }
    __syncthreads();
    for (int idx = tid; idx < 1536; idx += 256) {
        int tok = idx / 48, c4 = idx % 48;
        float4 v = *(const float4*)&v_s[tok * 196 + c4 * 4];
        float4 lw = *(const float4*)&ln_w[c4 * 4];
        float4 lb = *(const float4*)&ln_b[c4 * 4];
        float mu = mu_s[tok], rs = rs_s[tok];
        v.x = (v.x - mu) * rs * lw.x + lb.x; v.y = (v.y - mu) * rs * lw.y + lb.y;
        v.z = (v.z - mu) * rs * lw.z + lb.z; v.w = (v.w - mu) * rs * lw.w + lb.w;
        *(float4*)&v_s[tok * 196 + c4 * 4] = v;
    }

    u64t acc[2][12];
    #pragma unroll
    for (int i = 0; i < 2; i++)
        #pragma unroll
        for (int j = 0; j < 12; j++) acc[i][j] = 0ull;

    for (int kc = 0; kc < 6; kc++) {
        __syncthreads();
        for (int idx = tid; idx < 3072; idx += 256) {
            int kp = idx / 192, o = idx % 192;
            Bs[kp * 192 + o] = *(const float2*)&out_w[o * DIM + kc * 32 + kp * 2];
        }
        __syncthreads();
        for (int kp = 0; kp < 16; kp += 2) {
            ulonglong2 aA[2];
            #pragma unroll
            for (int i = 0; i < 2; i++)
                aA[i] = *(const ulonglong2*)&v_s[(ty * 2 + i) * 196 + kc * 32 + kp * 2];
            {
                const ulonglong2* bp = (const ulonglong2*)&Bs[kp * 192 + tx * 12];
                u64t bv[12];
                #pragma unroll
                for (int q = 0; q < 6; q++) { ulonglong2 t = bp[q]; bv[2*q] = t.x; bv[2*q+1] = t.y; }
                #pragma unroll
                for (int i = 0; i < 2; i++)
                    #pragma unroll
                    for (int j = 0; j < 12; j++)
                        acc[i][j] = ffma2(aA[i].x, bv[j], acc[i][j]);
            }
            {
                const ulonglong2* bp = (const ulonglong2*)&Bs[(kp + 1) * 192 + tx * 12];
                u64t bv[12];
                #pragma unroll
                for (int q = 0; q < 6; q++) { ulonglong2 t = bp[q]; bv[2*q] = t.x; bv[2*q+1] = t.y; }
                #pragma unroll
                for (int i = 0; i < 2; i++)
                    #pragma unroll
                    for (int j = 0; j < 12; j++)
                        acc[i][j] = ffma2(aA[i].y, bv[j], acc[i][j]);
            }
        }
    }

    float bb[12];
    #pragma unroll
    for (int j = 0; j < 12; j++) bb[j] = out_b[tx * 12 + j];
    #pragma unroll
    for (int i = 0; i < 2; i++) {
        int l = l0 + ty * 2 + i;
        float r[12];
        #pragma unroll
        for (int j = 0; j < 12; j++) r[j] = lohi_sum(acc[i][j]) + bb[j];
        float* op = out + (size_t)l * DIM + tx * 12;
        *(float4*)(op + 0) = make_float4(r[0], r[1], r[2], r[3]);
        *(float4*)(op + 4) = make_float4(r[4], r[5], r[6], r[7]);
        *(float4*)(op + 8) = make_float4(r[8], r[9], r[10], r[11]);
    }
}

// ---------------- launch ----------------
extern "C" void kernel_launch(void* const* d_in, const int* in_sizes, int n_in,
                              void* d_out, int out_size) {
    const float* x        = (const float*)d_in[0];
    const float* gumbel_u = (const float*)d_in[1];
    const float* conv1_w  = (const float*)d_in[2];
    const float* conv1_b  = (const float*)d_in[3];
    const float* conv2_w  = (const float*)d_in[4];
    const float* conv2_b  = (const float*)d_in[5];
    const float* route1_w = (const float*)d_in[6];
    const float* route1_b = (const float*)d_in[7];
    const float* route2_w = (const float*)d_in[8];
    const float* route2_b = (const float*)d_in[9];
    const float* Dv       = (const float*)d_in[11];
    const float* ln_w     = (const float*)d_in[12];
    const float* ln_b     = (const float*)d_in[13];
    const float* out_w    = (const float*)d_in[14];
    const float* out_b    = (const float*)d_in[15];
    const float* emb      = (const float*)d_in[16];
    float* out = (float*)d_out;

    int route_smem = (64 * 196 + 32 * 96 * 2 + 64 * 100 + 768 + 64 * 9 + 16) * (int)sizeof(float);
    int final_smem = (32 * 196 + 16 * 192 * 2 + 64 + 16) * (int)sizeof(float);
    static int attr_done = 0;
    if (!attr_done) {
        cudaFuncSetAttribute(k_route, cudaFuncAttributeMaxDynamicSharedMemorySize, route_smem);
        cudaFuncSetAttribute(k_final, cudaFuncAttributeMaxDynamicSharedMemorySize, final_smem);
        attr_done = 1;
    }

    k_intensity<<<L_TOT / 256, 256>>>(x);
    k_conv1<<<dim3(L_TOT / 256, C1), 256>>>(conv1_w, conv1_b);
    k_conv2<<<3 * (L_TOT / 128), 256>>>(conv2_w, conv2_b);
    k_route<<<L_TOT / 64, 256, route_smem>>>(x, route1_w, route1_b, route2_w, route2_b,
                                             gumbel_u, emb);
    k_final<<<L_TOT / 32, 256, final_smem>>>(x, Dv, ln_w, ln_b, out_w, out_b, out);
}

// round 6
// speedup vs baseline: 1.7443x; 1.7443x over previous
#include <cuda_runtime.h>
#include <math.h>
#include <stdint.h>

#define L_TOT  65536
#define HDIM   256
#define WDIM   256
#define DIM    192
#define C1     48
#define NTOK   8

typedef unsigned long long u64t;

__device__ __forceinline__ u64t ffma2(u64t a, u64t b, u64t c) {
    u64t d;
    asm("fma.rn.f32x2 %0, %1, %2, %3;" : "=l"(d) : "l"(a), "l"(b), "l"(c));
    return d;
}
union F2u { u64t u; float2 f; };
__device__ __forceinline__ float lohi_sum(u64t v) { F2u t; t.u = v; return t.f.x + t.f.y; }

// ---------------- scratch ----------------
__device__ float  g_intensity[L_TOT];
__device__ float2 g_f1p[(C1 / 2) * L_TOT];     // conv1 out, ic-pair interleaved [icp][l]
__device__ float  g_feat[(size_t)L_TOT * DIM]; // conv2 out, token-major [l][c]
__device__ float  g_gamma[L_TOT];
__device__ float  g_beta[L_TOT];
__device__ float2 g_w2t[24 * 9 * 192];         // conv2 w transposed: [(icp*9+kp)*192 + oc]
__device__ float2 g_owt[96 * 192];             // out_w transposed: [kp*192 + o] = (w[o][2kp], w[o][2kp+1])

// ---------------- K0: weight transpose prep ----------------
__global__ void k_prep(const float* __restrict__ w2, const float* __restrict__ out_w) {
    int idx = blockIdx.x * 256 + threadIdx.x;
    if (idx < 41472) {
        int icp = idx / 1728;
        int r = idx - icp * 1728;
        int kp = r / 192, oc = r - kp * 192;
        const float* base = w2 + (size_t)oc * 432 + icp * 18 + kp;
        g_w2t[idx] = make_float2(base[0], base[9]);
    }
    int j = idx - 41472;
    if (j >= 0 && j < 18432) {
        int kp = j / 192, o = j - kp * 192;
        g_owt[j] = make_float2(out_w[o * DIM + kp * 2], out_w[o * DIM + kp * 2 + 1]);
    }
}

// ---------------- K1: intensity ----------------
__global__ void k_intensity(const float* __restrict__ x) {
    int l = blockIdx.x * 256 + threadIdx.x;
    const float* p = x + (size_t)l * DIM;
    g_intensity[l] = 0.299f * p[0] + 0.587f * p[1] + 0.114f * p[2];
}

// ---------------- K2: conv1 1->48, 3x3 SAME, LeakyReLU(0.2) ----------------
__global__ void k_conv1(const float* __restrict__ w, const float* __restrict__ b) {
    int l  = blockIdx.x * 256 + threadIdx.x;
    int oc = blockIdx.y;
    int y = l >> 8, xx = l & 255;
    float acc = b[oc];
    #pragma unroll
    for (int ky = 0; ky < 3; ky++) {
        int gy = y + ky - 1;
        if (gy < 0 || gy >= HDIM) continue;
        #pragma unroll
        for (int kx = 0; kx < 3; kx++) {
            int gx = xx + kx - 1;
            if (gx < 0 || gx >= WDIM) continue;
            acc += w[oc * 9 + ky * 3 + kx] * g_intensity[(gy << 8) + gx];
        }
    }
    acc = (acc > 0.f) ? acc : 0.2f * acc;
    ((float*)g_f1p)[((size_t)(oc >> 1) * L_TOT + l) * 2 + (oc & 1)] = acc;
}

// ---------------- K3: conv2 48->192, 3x3 SAME (ic-pair f32x2, conflict-free) -------
// Block: 64 pix x 64 oc, 256 thr. Thread: 2 pix x 8 oc (oc pairs {2tx+16j, 2tx+16j+1}).
// b loads: 4x LDS.128 at 16B-lane-contiguous addresses (1 wavefront each, ty-broadcast).
__global__ __launch_bounds__(256) void k_conv2(const float* __restrict__ b2) {
    __shared__ __align__(16) float2 Ws2[9][64];   // [kp][oc-local]
    __shared__ __align__(16) float2 Ps2[9][64];   // [kp][pix-local]
    int tid = threadIdx.x;
    int oc0 = (blockIdx.x % 3) * 64;
    int p0  = (blockIdx.x / 3) * 64;
    int y  = p0 >> 8;
    int x0 = p0 & 255;
    int tx = tid & 7;    // oc lane
    int ty = tid >> 3;   // pix: ty*2 + i  (0..31)

    u64t acc[2][8];
    #pragma unroll
    for (int i = 0; i < 2; i++)
        #pragma unroll
        for (int j = 0; j < 8; j++) acc[i][j] = 0ull;

    for (int icp = 0; icp < 24; icp++) {
        __syncthreads();
        // stage weights from transposed layout (coalesced)
        for (int idx = tid; idx < 576; idx += 256) {
            int kp = idx >> 6, ocl = idx & 63;
            Ws2[kp][ocl] = g_w2t[(icp * 9 + kp) * 192 + oc0 + ocl];
        }
        // stage shifted pixel rows
        for (int idx = tid; idx < 576; idx += 256) {
            int kp = idx >> 6, p = idx & 63;
            int ky = kp / 3, kx = kp - ky * 3;
            int gy = y + ky - 1, gx = x0 + p + kx - 1;
            float2 v = make_float2(0.f, 0.f);
            if (gy >= 0 && gy < HDIM && gx >= 0 && gx < WDIM)
                v = g_f1p[(size_t)icp * L_TOT + (gy << 8) + gx];
            Ps2[kp][p] = v;
        }
        __syncthreads();
        #pragma unroll
        for (int kp = 0; kp < 9; kp++) {
            ulonglong2 av = *(const ulonglong2*)&Ps2[kp][ty * 2];
            ulonglong2 b0 = *(const ulonglong2*)&Ws2[kp][tx * 2];
            ulonglong2 b1 = *(const ulonglong2*)&Ws2[kp][tx * 2 + 16];
            ulonglong2 b2v = *(const ulonglong2*)&Ws2[kp][tx * 2 + 32];
            ulonglong2 b3 = *(const ulonglong2*)&Ws2[kp][tx * 2 + 48];
            u64t bv[8] = {b0.x, b0.y, b1.x, b1.y, b2v.x, b2v.y, b3.x, b3.y};
            #pragma unroll
            for (int j = 0; j < 8; j++) {
                acc[0][j] = ffma2(av.x, bv[j], acc[0][j]);
                acc[1][j] = ffma2(av.y, bv[j], acc[1][j]);
            }
        }
    }

    float bj[8];
    #pragma unroll
    for (int jj = 0; jj < 4; jj++) {
        bj[2 * jj]     = b2[oc0 + tx * 2 + jj * 16];
        bj[2 * jj + 1] = b2[oc0 + tx * 2 + jj * 16 + 1];
    }
    #pragma unroll
    for (int i = 0; i < 2; i++) {
        int l = p0 + ty * 2 + i;
        float* op = g_feat + (size_t)l * DIM + oc0;
        #pragma unroll
        for (int jj = 0; jj < 4; jj++) {
            float2 o = make_float2(lohi_sum(acc[i][2 * jj]) + bj[2 * jj],
                                   lohi_sum(acc[i][2 * jj + 1]) + bj[2 * jj + 1]);
            *(float2*)(op + tx * 2 + jj * 16) = o;
        }
    }
}

// ---------------- K4: routing MLP + softmax + gumbel argmax (Round-1 proven) -------
__global__ __launch_bounds__(256) void k_route(const float* __restrict__ x,
                                               const float* __restrict__ w1,
                                               const float* __restrict__ b1,
                                               const float* __restrict__ w2,
                                               const float* __restrict__ b2r,
                                               const float* __restrict__ gumbel,
                                               const float* __restrict__ emb) {
    __shared__ float z_s[64][17];
    __shared__ float W1s[16][97];
    __shared__ float hm_s[64][97];
    __shared__ float W2s[8][96];
    __shared__ float lg_s[64][9];
    int tid = threadIdx.x;
    int t0base = blockIdx.x * 64;
    int tx = tid & 15;   // hmid group: tx*6 + jj
    int ty = tid >> 4;   // tok group:  ty*4 + i

    for (int idx = tid; idx < 768; idx += 256)
        W2s[idx / 96][idx % 96] = w2[idx];

    float acc[4][6];
    #pragma unroll
    for (int i = 0; i < 4; i++)
        #pragma unroll
        for (int jj = 0; jj < 6; jj++) acc[i][jj] = 0.f;

    for (int k0 = 0; k0 < DIM; k0 += 16) {
        __syncthreads();
        for (int idx = tid; idx < 1024; idx += 256) {
            int tok = idx >> 4, kk = idx & 15;
            size_t off = (size_t)(t0base + tok) * DIM + k0 + kk;
            z_s[tok][kk] = x[off] + 0.3f * g_feat[off];
        }
        for (int idx = tid; idx < 1536; idx += 256) {
            int j = idx >> 4, kk = idx & 15;
            W1s[kk][j] = w1[j * DIM + k0 + kk];
        }
        __syncthreads();
        #pragma unroll
        for (int kk = 0; kk < 16; kk++) {
            float a[4], b[6];
            #pragma unroll
            for (int i = 0; i < 4; i++) a[i] = z_s[ty * 4 + i][kk];
            #pragma unroll
            for (int jj = 0; jj < 6; jj++) b[jj] = W1s[kk][tx * 6 + jj];
            #pragma unroll
            for (int i = 0; i < 4; i++)
                #pragma unroll
                for (int jj = 0; jj < 6; jj++) acc[i][jj] += a[i] * b[jj];
        }
    }
    __syncthreads();
    #pragma unroll
    for (int jj = 0; jj < 6; jj++) {
        float bb = b1[tx * 6 + jj];
        #pragma unroll
        for (int i = 0; i < 4; i++) {
            float v = acc[i][jj] + bb;
            v = 0.5f * v * (1.0f + erff(v * 0.7071067811865476f));  // exact GELU
            hm_s[ty * 4 + i][tx * 6 + jj] = v;
        }
    }
    __syncthreads();
    #pragma unroll
    for (int half = 0; half < 2; half++) {
        int tok = (tid >> 3) + half * 32;
        int t = tid & 7;
        float s = b2r[t];
        #pragma unroll 8
        for (int j = 0; j < 96; j++) s += hm_s[tok][j] * W2s[t][j];
        lg_s[tok][t] = s;
    }
    __syncthreads();
    if (tid < 64) {
        int tok = tid;
        int l = t0base + tok;
        float mx = -1e30f;
        #pragma unroll
        for (int t = 0; t < NTOK; t++) mx = fmaxf(mx, lg_s[tok][t]);
        float e[NTOK], sum = 0.f;
        #pragma unroll
        for (int t = 0; t < NTOK; t++) { e[t] = expf(lg_s[tok][t] - mx); sum += e[t]; }
        float inv = 1.0f / sum;
        float inten = g_intensity[l];
        float best = -1e30f; int kbest = 0; float rw0 = 0.f;
        #pragma unroll
        for (int t = 0; t < NTOK; t++) {
            float rw = e[t] * inv;
            if (t == 0) rw0 = rw;
            float sim = 1.0f - fabsf(emb[t] - inten);
            float u = gumbel[(size_t)l * NTOK + t];
            u = fmaxf(u, 1e-10f);
            float g = -logf(-logf(u));
            float sc = rw * sim + g;
            if (sc > best) { best = sc; kbest = t; }
        }
        float ek = emb[kbest];
        g_gamma[l] = 0.3f + 0.7f / (1.0f + expf(-ek));
        g_beta[l]  = rw0 - 0.5f;
    }
}

// ---------------- K5: v=D*(gamma*x+beta), LayerNorm, out = yn@out_w^T + b ----------
// 64 tok/block, 512 threads. f32x2 k-pairs, thread tile 2 tok x 12 oc (oc = tx+16j),
// b-loads 16-lane-contiguous LDS.64 (1 wavefront, ty-broadcast).
__global__ __launch_bounds__(512) void k_final(const float* __restrict__ x,
                                               const float* __restrict__ Dv,
                                               const float* __restrict__ ln_w,
                                               const float* __restrict__ ln_b,
                                               const float* __restrict__ out_b,
                                               float* __restrict__ out) {
    extern __shared__ float sh[];
    float*  v_s  = sh;                         // [64][196]
    float2* Bs   = (float2*)(sh + 64 * 196);   // [16][192]
    float*  mu_s = sh + 64 * 196 + 16 * 192 * 2; // [64]
    float*  rs_s = mu_s + 64;                  // [64]

    int tid = threadIdx.x;
    int l0 = blockIdx.x * 64;
    int tx = tid & 15;   // oc lane: oc = tx + 16*j
    int ty = tid >> 4;   // tok: ty*2 + i   (0..31)

    for (int idx = tid; idx < 3072; idx += 512) {
        int tok = idx / 48, c4 = idx % 48;
        int l = l0 + tok;
        float4 xv = *(const float4*)&x[(size_t)l * DIM + c4 * 4];
        float4 dv = *(const float4*)&Dv[c4 * 4];
        float g = g_gamma[l], b = g_beta[l];
        float4 v;
        v.x = dv.x * (g * xv.x + b); v.y = dv.y * (g * xv.y + b);
        v.z = dv.z * (g * xv.z + b); v.w = dv.w * (g * xv.w + b);
        *(float4*)&v_s[tok * 196 + c4 * 4] = v;
    }
    __syncthreads();
    {
        int tok = tid >> 3, l8 = tid & 7;
        float s = 0.f, sq = 0.f;
        for (int c = l8; c < DIM; c += 8) {
            float v = v_s[tok * 196 + c];
            s += v; sq += v * v;
        }
        #pragma unroll
        for (int off = 4; off > 0; off >>= 1) {
            s  += __shfl_down_sync(0xffffffffu, s, off);
            sq += __shfl_down_sync(0xffffffffu, sq, off);
        }
        if (l8 == 0) {
            float mu = s * (1.0f / DIM);
            float var = sq * (1.0f / DIM) - mu * mu;
            mu_s[tok] = mu;
            rs_s[tok] = rsqrtf(var + 1e-5f);
        }
    }
    __syncthreads();
    for (int idx = tid; idx < 3072; idx += 512) {
        int tok = idx / 48, c4 = idx % 48;
        float4 v = *(const float4*)&v_s[tok * 196 + c4 * 4];
        float4 lw = *(const float4*)&ln_w[c4 * 4];
        float4 lb = *(const float4*)&ln_b[c4 * 4];
        float mu = mu_s[tok], rs = rs_s[tok];
        v.x = (v.x - mu) * rs * lw.x + lb.x; v.y = (v.y - mu) * rs * lw.y + lb.y;
        v.z = (v.z - mu) * rs * lw.z + lb.z; v.w = (v.w - mu) * rs * lw.w + lb.w;
        *(float4*)&v_s[tok * 196 + c4 * 4] = v;
    }

    u64t acc[2][12];
    #pragma unroll
    for (int i = 0; i < 2; i++)
        #pragma unroll
        for (int j = 0; j < 12; j++) acc[i][j] = 0ull;

    for (int kc = 0; kc < 6; kc++) {
        __syncthreads();
        // stage 16 k-pairs x 192 oc from transposed out_w (coalesced)
        for (int idx = tid; idx < 3072; idx += 512)
            Bs[idx] = g_owt[kc * 3072 + idx];
        __syncthreads();
        #pragma unroll
        for (int kp = 0; kp < 16; kp++) {
            u64t a0 = *(const u64t*)&v_s[(ty * 2 + 0) * 196 + kc * 32 + kp * 2];
            u64t a1 = *(const u64t*)&v_s[(ty * 2 + 1) * 196 + kc * 32 + kp * 2];
            #pragma unroll
            for (int j = 0; j < 12; j++) {
                u64t bv = *(const u64t*)&Bs[kp * 192 + tx + 16 * j];
                acc[0][j] = ffma2(a0, bv, acc[0][j]);
                acc[1][j] = ffma2(a1, bv, acc[1][j]);
            }
        }
    }

    float bb[12];
    #pragma unroll
    for (int j = 0; j < 12; j++) bb[j] = out_b[tx + 16 * j];
    #pragma unroll
    for (int i = 0; i < 2; i++) {
        int l = l0 + ty * 2 + i;
        float* op = out + (size_t)l * DIM;
        #pragma unroll
        for (int j = 0; j < 12; j++)
            op[tx + 16 * j] = lohi_sum(acc[i][j]) + bb[j];
    }
}

// ---------------- launch ----------------
extern "C" void kernel_launch(void* const* d_in, const int* in_sizes, int n_in,
                              void* d_out, int out_size) {
    const float* x        = (const float*)d_in[0];
    const float* gumbel_u = (const float*)d_in[1];
    const float* conv1_w  = (const float*)d_in[2];
    const float* conv1_b  = (const float*)d_in[3];
    const float* conv2_w  = (const float*)d_in[4];
    const float* conv2_b  = (const float*)d_in[5];
    const float* route1_w = (const float*)d_in[6];
    const float* route1_b = (const float*)d_in[7];
    const float* route2_w = (const float*)d_in[8];
    const float* route2_b = (const float*)d_in[9];
    const float* Dv       = (const float*)d_in[11];
    const float* ln_w     = (const float*)d_in[12];
    const float* ln_b     = (const float*)d_in[13];
    const float* out_w    = (const float*)d_in[14];
    const float* out_b    = (const float*)d_in[15];
    const float* emb      = (const float*)d_in[16];
    float* out = (float*)d_out;

    int final_smem = (64 * 196 + 16 * 192 * 2 + 128 + 16) * (int)sizeof(float);
    static int attr_done = 0;
    if (!attr_done) {
        cudaFuncSetAttribute(k_final, cudaFuncAttributeMaxDynamicSharedMemorySize, final_smem);
        attr_done = 1;
    }

    k_prep<<<(41472 + 18432 + 255) / 256, 256>>>(conv2_w, out_w);
    k_intensity<<<L_TOT / 256, 256>>>(x);
    k_conv1<<<dim3(L_TOT / 256, C1), 256>>>(conv1_w, conv1_b);
    k_conv2<<<3 * (L_TOT / 64), 256>>>(conv2_b);
    k_route<<<L_TOT / 64, 256>>>(x, route1_w, route1_b, route2_w, route2_b,
                                 gumbel_u, emb);
    k_final<<<L_TOT / 64, 512, final_smem>>>(x, Dv, ln_w, ln_b, out_b, out);
}